// round 1
// baseline (speedup 1.0000x reference)
#include <cuda_runtime.h>
#include <cub/cub.cuh>

#define NP 268800
#define MAX_KEEP 750
#define IOU_THR 0.4f
#define NMS_T 1024

// ---------------- scratch (static device globals; no runtime alloc) ----------------
__device__ float4        g_boxes[NP];
__device__ unsigned      g_keys[NP];
__device__ unsigned      g_vals[NP];
__device__ unsigned      g_keys_s[NP];
__device__ unsigned      g_vals_s[NP];
__device__ int           g_kept[MAX_KEEP];
__device__ unsigned char g_temp[16 * 1024 * 1024];

// ---------------- priors computed on the fly (fp64 like numpy, cast to f32) --------
__device__ __forceinline__ void get_prior(int i, float& px, float& py, float& ps) {
    int j = i, f, step;
    double mins;
    if (j < 204800)      { f = 320; step = 8;  mins = (j & 1) ? 32.0  : 16.0;  }
    else if (j < 256000) { j -= 204800; f = 160; step = 16; mins = (j & 1) ? 128.0 : 64.0;  }
    else                 { j -= 256000; f = 80;  step = 32; mins = (j & 1) ? 512.0 : 256.0; }
    int cell = j >> 1;
    int y = cell / f;
    int x = cell - y * f;
    px = (float)(((double)x + 0.5) * (double)step / 2560.0);
    py = (float)(((double)y + 0.5) * (double)step / 2560.0);
    ps = (float)(mins / 2560.0);
}

// ---------------- K1: decode boxes + build sort keys -------------------------------
__global__ void decode_kernel(const float* __restrict__ bb,
                              const float* __restrict__ sc,
                              const float* __restrict__ thrp) {
    int i = blockIdx.x * blockDim.x + threadIdx.x;
    if (i >= NP) return;
    float px, py, ps;
    get_prior(i, px, py, ps);
    float lx = bb[4 * i + 0], ly = bb[4 * i + 1];
    float lw = bb[4 * i + 2], lh = bb[4 * i + 3];
    float cx = px + lx * 0.1f * ps;
    float cy = py + ly * 0.1f * ps;
    float w  = ps * expf(lw * 0.2f);
    float h  = ps * expf(lh * 0.2f);
    float x1 = (cx - w * 0.5f) * 2560.0f;
    float y1 = (cy - h * 0.5f) * 2560.0f;
    float x2 = (cx + w * 0.5f) * 2560.0f;
    float y2 = (cy + h * 0.5f) * 2560.0f;
    g_boxes[i] = make_float4(x1, y1, x2, y2);
    float s = sc[i];
    float thr = thrp[0];
    // key: descending score (positive floats -> ~bits monotone), stable radix keeps
    // index-ascending tie order == jnp.argsort(-scores, stable)
    g_keys[i] = (s > thr) ? ~__float_as_uint(s) : 0xFFFFFFFFu;
    g_vals[i] = (unsigned)i;
}

// ---------------- K3: greedy NMS, single block, kept list in smem ------------------
__global__ void __launch_bounds__(NMS_T, 1)
nms_kernel(const unsigned* __restrict__ skeys,
           const unsigned* __restrict__ svals,
           int n) {
    __shared__ float kx1[MAX_KEEP], ky1[MAX_KEEP], kx2[MAX_KEEP], ky2[MAX_KEEP], kar[MAX_KEEP];
    __shared__ int   kid[MAX_KEEP];
    __shared__ float cx1[NMS_T], cy1[NMS_T], cx2[NMS_T], cy2[NMS_T], car[NMS_T];
    __shared__ int   cid[NMS_T];
    __shared__ unsigned amask[NMS_T / 32];
    __shared__ int s_nk, s_j;

    int tid  = threadIdx.x;
    int lane = tid & 31;
    int warp = tid >> 5;
    if (tid == 0) s_nk = 0;
    __syncthreads();

    for (int base = 0; base < n; base += NMS_T) {
        int nk0 = s_nk;
        if (nk0 >= MAX_KEEP) break;
        if (skeys[base] == 0xFFFFFFFFu) break;  // sorted: rest are below threshold

        int t = base + tid;
        bool alive = false;
        float x1 = 0.f, y1 = 0.f, x2 = 0.f, y2 = 0.f, ar = 0.f;
        int oi = -1;
        if (t < n) {
            unsigned key = skeys[t];
            if (key != 0xFFFFFFFFu) {
                oi = (int)svals[t];
                float4 b = g_boxes[oi];
                x1 = b.x; y1 = b.y; x2 = b.z; y2 = b.w;
                ar = (x2 - x1 + 1.0f) * (y2 - y1 + 1.0f);
                alive = true;
            }
        }
        cx1[tid] = x1; cy1[tid] = y1; cx2[tid] = x2; cy2[tid] = y2;
        car[tid] = ar; cid[tid] = oi;

        // check against already-kept boxes (early exit on suppression)
        for (int k = 0; k < nk0; ++k) {
            if (!alive) break;
            float xx1 = fmaxf(kx1[k], x1), yy1 = fmaxf(ky1[k], y1);
            float xx2 = fminf(kx2[k], x2), yy2 = fminf(ky2[k], y2);
            float inter = fmaxf(0.0f, xx2 - xx1 + 1.0f) * fmaxf(0.0f, yy2 - yy1 + 1.0f);
            float iou = inter / (kar[k] + ar - inter);
            if (iou > IOU_THR) alive = false;
        }

        // serial in-batch resolution: repeatedly take lowest alive position
        for (;;) {
            unsigned m = __ballot_sync(0xFFFFFFFFu, alive);
            if (lane == 0) amask[warp] = m;
            __syncthreads();
            if (tid == 0) {
                int j = -1;
                int nk = s_nk;
                if (nk < MAX_KEEP) {
                    #pragma unroll
                    for (int w = 0; w < NMS_T / 32; ++w) {
                        unsigned mm = amask[w];
                        if (mm) { j = w * 32 + __ffs(mm) - 1; break; }
                    }
                }
                if (j >= 0) {
                    kx1[nk] = cx1[j]; ky1[nk] = cy1[j];
                    kx2[nk] = cx2[j]; ky2[nk] = cy2[j];
                    kar[nk] = car[j]; kid[nk] = cid[j];
                    s_nk = nk + 1;
                }
                s_j = j;
            }
            __syncthreads();
            int j = s_j;
            if (j < 0) break;
            if (alive) {
                if (tid == j) {
                    alive = false;
                } else if (tid > j) {
                    float xx1 = fmaxf(cx1[j], x1), yy1 = fmaxf(cy1[j], y1);
                    float xx2 = fminf(cx2[j], x2), yy2 = fminf(cy2[j], y2);
                    float inter = fmaxf(0.0f, xx2 - xx1 + 1.0f) * fmaxf(0.0f, yy2 - yy1 + 1.0f);
                    float iou = inter / (car[j] + ar - inter);
                    if (iou > IOU_THR) alive = false;
                }
            }
        }
    }

    __syncthreads();
    int nk = s_nk;
    for (int i = tid; i < MAX_KEEP; i += blockDim.x)
        g_kept[i] = (i < nk) ? kid[i] : -1;
}

// ---------------- K4: gather outputs (boxes | scores | landmarks) ------------------
__global__ void output_kernel(const float* __restrict__ sc,
                              const float* __restrict__ lm,
                              float* __restrict__ out) {
    int slot = blockIdx.x * blockDim.x + threadIdx.x;
    if (slot >= MAX_KEEP) return;
    int idx = g_kept[slot];
    float b0 = 0.f, b1 = 0.f, b2 = 0.f, b3 = 0.f, s = 0.f;
    float l[10];
    #pragma unroll
    for (int k = 0; k < 10; ++k) l[k] = 0.f;
    if (idx >= 0) {
        float4 b = g_boxes[idx];
        b0 = b.x; b1 = b.y; b2 = b.z; b3 = b.w;
        s = sc[idx];
        float px, py, ps;
        get_prior(idx, px, py, ps);
        #pragma unroll
        for (int k = 0; k < 5; ++k) {
            float ox = lm[10 * idx + 2 * k + 0];
            float oy = lm[10 * idx + 2 * k + 1];
            l[2 * k + 0] = (px + ox * 0.1f * ps) * 2560.0f;
            l[2 * k + 1] = (py + oy * 0.1f * ps) * 2560.0f;
        }
    }
    out[slot * 4 + 0] = b0;
    out[slot * 4 + 1] = b1;
    out[slot * 4 + 2] = b2;
    out[slot * 4 + 3] = b3;
    out[3000 + slot] = s;
    #pragma unroll
    for (int k = 0; k < 10; ++k)
        out[3750 + slot * 10 + k] = l[k];
}

// ---------------- launch ----------------------------------------------------------
extern "C" void kernel_launch(void* const* d_in, const int* in_sizes, int n_in,
                              void* d_out, int out_size) {
    const float* bb  = (const float*)d_in[0];
    const float* sc  = (const float*)d_in[1];
    const float* lm  = (const float*)d_in[2];
    const float* thr = (const float*)d_in[3];
    float* out = (float*)d_out;

    void *pk, *pv, *pks, *pvs, *ptmp;
    cudaGetSymbolAddress(&pk,   g_keys);
    cudaGetSymbolAddress(&pv,   g_vals);
    cudaGetSymbolAddress(&pks,  g_keys_s);
    cudaGetSymbolAddress(&pvs,  g_vals_s);
    cudaGetSymbolAddress(&ptmp, g_temp);

    decode_kernel<<<NP / 256, 256>>>(bb, sc, thr);

    size_t tb = 0;
    cub::DeviceRadixSort::SortPairs(nullptr, tb,
                                    (const unsigned*)pk, (unsigned*)pks,
                                    (const unsigned*)pv, (unsigned*)pvs,
                                    NP, 0, 32, (cudaStream_t)0);
    cub::DeviceRadixSort::SortPairs(ptmp, tb,
                                    (const unsigned*)pk, (unsigned*)pks,
                                    (const unsigned*)pv, (unsigned*)pvs,
                                    NP, 0, 32, (cudaStream_t)0);

    nms_kernel<<<1, NMS_T>>>((const unsigned*)pks, (const unsigned*)pvs, NP);

    output_kernel<<<(MAX_KEEP + 127) / 128, 128>>>(sc, lm, out);
}

// round 2
// speedup vs baseline: 5.7399x; 5.7399x over previous
#include <cuda_runtime.h>
#include <cub/cub.cuh>

#define NP 268800
#define MAX_KEEP 750
#define IOU_THR 0.4f
#define H 1024
#define HW (H / 32)              // 32 words per row
#define INVALID_KEY 0xFFFFFFFFu
#define FULL 0xFFFFFFFFu

// ---------------- scratch (static device globals; no runtime alloc) ----------------
__device__ float4        g_boxes[NP];
__device__ unsigned      g_keys[NP];
__device__ unsigned      g_vals[NP];
__device__ unsigned      g_keys_s[NP];
__device__ unsigned      g_vals_s[NP];
__device__ int           g_kept[MAX_KEEP];
__device__ unsigned char g_temp[16 * 1024 * 1024];
// top-H candidate cache + edge matrix + done flag
__device__ float4        g_cbox[H];
__device__ float         g_car[H];
__device__ int           g_cval[H];
__device__ int           g_cidx[H];
__device__ unsigned      g_E[H * HW];    // E[j]: bitmask of earlier (i<j) IoU-neighbors
__device__ int           g_done;

// ---------------- priors computed on the fly (fp64 like numpy, cast to f32) --------
__device__ __forceinline__ void get_prior(int i, float& px, float& py, float& ps) {
    int j = i, f, step;
    double mins;
    if (j < 204800)      { f = 320; step = 8;  mins = (j & 1) ? 32.0  : 16.0;  }
    else if (j < 256000) { j -= 204800; f = 160; step = 16; mins = (j & 1) ? 128.0 : 64.0;  }
    else                 { j -= 256000; f = 80;  step = 32; mins = (j & 1) ? 512.0 : 256.0; }
    int cell = j >> 1;
    int y = cell / f;
    int x = cell - y * f;
    px = (float)(((double)x + 0.5) * (double)step / 2560.0);
    py = (float)(((double)y + 0.5) * (double)step / 2560.0);
    ps = (float)(mins / 2560.0);
}

__device__ __forceinline__ bool iou_gt(float x1, float y1, float x2, float y2, float ar,
                                       float bx1, float by1, float bx2, float by2, float bar) {
    float xx1 = fmaxf(x1, bx1), yy1 = fmaxf(y1, by1);
    float xx2 = fminf(x2, bx2), yy2 = fminf(y2, by2);
    float inter = fmaxf(0.0f, xx2 - xx1 + 1.0f) * fmaxf(0.0f, yy2 - yy1 + 1.0f);
    float iou = inter / (ar + bar - inter);
    return iou > IOU_THR;
}

// ---------------- K1: decode boxes + build sort keys -------------------------------
__global__ void decode_kernel(const float* __restrict__ bb,
                              const float* __restrict__ sc,
                              const float* __restrict__ thrp) {
    int i = blockIdx.x * blockDim.x + threadIdx.x;
    if (i >= NP) return;
    float px, py, ps;
    get_prior(i, px, py, ps);
    float lx = bb[4 * i + 0], ly = bb[4 * i + 1];
    float lw = bb[4 * i + 2], lh = bb[4 * i + 3];
    float cx = px + lx * 0.1f * ps;
    float cy = py + ly * 0.1f * ps;
    float w  = ps * expf(lw * 0.2f);
    float h  = ps * expf(lh * 0.2f);
    g_boxes[i] = make_float4((cx - w * 0.5f) * 2560.0f, (cy - h * 0.5f) * 2560.0f,
                             (cx + w * 0.5f) * 2560.0f, (cy + h * 0.5f) * 2560.0f);
    float s = sc[i];
    float thr = thrp[0];
    // stable radix: key = ~bits(score) -> (score desc, index asc), exactly argsort(-scores)
    g_keys[i] = (s > thr) ? ~__float_as_uint(s) : INVALID_KEY;
    g_vals[i] = (unsigned)i;
}

// ---------------- K2: gather top-H candidates --------------------------------------
__global__ void gather_kernel(const unsigned* __restrict__ skeys,
                              const unsigned* __restrict__ svals) {
    int i = blockIdx.x * blockDim.x + threadIdx.x;
    if (i >= H) return;
    unsigned key = skeys[i];
    bool valid = (key != INVALID_KEY);
    float4 b = make_float4(0.f, 0.f, 0.f, 0.f);
    int oi = -1;
    if (valid) { oi = (int)svals[i]; b = g_boxes[oi]; }
    g_cbox[i] = b;
    g_car[i]  = (b.z - b.x + 1.0f) * (b.w - b.y + 1.0f);
    g_cval[i] = valid ? 1 : 0;
    g_cidx[i] = oi;
}

// ---------------- K3: pairwise earlier-neighbor edge matrix (multi-SM) -------------
__global__ void edges_kernel() {
    int j = (blockIdx.x * blockDim.x + threadIdx.x) >> 5;   // one warp per row
    int lane = threadIdx.x & 31;
    if (j >= H) return;
    float4 bj = g_cbox[j];
    float  aj = g_car[j];
    bool   vj = g_cval[j] != 0;
    unsigned myword = 0;
    #pragma unroll 4
    for (int w = 0; w < HW; ++w) {
        int i = w * 32 + lane;
        float4 bi = g_cbox[i];
        float  ai = g_car[i];
        bool pred = vj && (g_cval[i] != 0) && (i < j) &&
                    iou_gt(bj.x, bj.y, bj.z, bj.w, aj, bi.x, bi.y, bi.z, bi.w, ai);
        unsigned m = __ballot_sync(FULL, pred);
        if (lane == w) myword = m;
    }
    g_E[j * HW + lane] = myword;
}

// ---------------- K4: parallel greedy resolution (1 block) -------------------------
// kept(j) <=> valid(j) and no earlier kept neighbor. Resolve by rounds; first 750
// kept (in sorted order) == reference keep list.
__global__ void __launch_bounds__(H, 1)
resolve_kernel(const unsigned* __restrict__ skeys) {
    __shared__ unsigned dec[HW], kep[HW];
    __shared__ int woff[33];
    int tid = threadIdx.x;
    int lane = tid & 31;
    int warp = tid >> 5;

    unsigned E[HW];
    {
        const uint4* row = (const uint4*)&g_E[tid * HW];
        #pragma unroll
        for (int q = 0; q < HW / 4; ++q) {
            uint4 v = row[q];
            E[4 * q + 0] = v.x; E[4 * q + 1] = v.y; E[4 * q + 2] = v.z; E[4 * q + 3] = v.w;
        }
    }
    bool valid   = g_cval[tid] != 0;
    bool decided = !valid;
    bool kept    = false;

    {
        unsigned md = __ballot_sync(FULL, decided);
        if (lane == 0) { dec[warp] = md; kep[warp] = 0u; }
    }
    __syncthreads();

    for (int round = 0; round < 64; ++round) {
        if (!decided) {
            unsigned pend = 0, sup = 0;
            #pragma unroll
            for (int w = 0; w < HW; ++w) {
                unsigned d = dec[w], k = kep[w], e = E[w];
                pend |= e & ~d;
                sup  |= e & k;
            }
            if (pend == 0u) { decided = true; kept = (sup == 0u); }
        }
        __syncthreads();
        unsigned md = __ballot_sync(FULL, decided);
        unsigned mk = __ballot_sync(FULL, kept);
        if (lane == 0) { dec[warp] = md; kep[warp] = mk; }
        int nUnd = __syncthreads_count(decided ? 0 : 1);
        if (nUnd == 0) break;
    }

    // exact serial fallback for pathological chains (never triggers on real data)
    int rem = __syncthreads_count(decided ? 0 : 1);
    if (rem > 0) {
        if (tid == 0) {
            for (int v = 0; v < H; ++v) {
                int w = v >> 5, b = v & 31;
                if ((dec[w] >> b) & 1u) continue;
                unsigned sup = 0;
                for (int ww = 0; ww < HW; ++ww) sup |= g_E[v * HW + ww] & kep[ww];
                dec[w] |= 1u << b;
                if (sup == 0u) kep[w] |= 1u << b;
            }
        }
        __syncthreads();
        kept = (kep[tid >> 5] >> (tid & 31)) & 1u;
    }

    // rank kept candidates in order; write first MAX_KEEP
    unsigned m = __ballot_sync(FULL, kept);
    if (lane == 0) woff[warp] = __popc(m);
    __syncthreads();
    if (tid < 32) {
        int v = woff[tid];
        int ex = v;
        #pragma unroll
        for (int d = 1; d < 32; d <<= 1) {
            int t = __shfl_up_sync(FULL, ex, d);
            if (tid >= d) ex += t;
        }
        woff[tid] = ex - v;                 // exclusive
        if (tid == 31) woff[32] = ex;       // total
    }
    __syncthreads();
    int total = woff[32];

    if (tid < MAX_KEEP) g_kept[tid] = -1;
    __syncthreads();
    if (kept) {
        int rank = woff[warp] + __popc(m & ((1u << lane) - 1u));
        if (rank < MAX_KEEP) g_kept[rank] = g_cidx[tid];
    }
    if (tid == 0) {
        // done if we filled the cap, or there are no valid candidates beyond top-H
        g_done = (total >= MAX_KEEP) || (skeys[H] == INVALID_KEY) ? 1 : 0;
    }
}

// ---------------- K5: exact fallback NMS (gated; no-ops when g_done) ---------------
#define NMS_T 1024
__global__ void __launch_bounds__(NMS_T, 1)
nms_fallback_kernel(const unsigned* __restrict__ skeys,
                    const unsigned* __restrict__ svals,
                    int n) {
    if (g_done) return;
    __shared__ float kx1[MAX_KEEP], ky1[MAX_KEEP], kx2[MAX_KEEP], ky2[MAX_KEEP], kar[MAX_KEEP];
    __shared__ int   kid[MAX_KEEP];
    __shared__ float cx1[NMS_T], cy1[NMS_T], cx2[NMS_T], cy2[NMS_T], car[NMS_T];
    __shared__ int   cid[NMS_T];
    __shared__ unsigned amask[NMS_T / 32];
    __shared__ int s_nk, s_j;

    int tid  = threadIdx.x;
    int lane = tid & 31;
    int warp = tid >> 5;
    if (tid == 0) s_nk = 0;
    __syncthreads();

    for (int base = 0; base < n; base += NMS_T) {
        int nk0 = s_nk;
        if (nk0 >= MAX_KEEP) break;
        if (skeys[base] == INVALID_KEY) break;

        int t = base + tid;
        bool alive = false;
        float x1 = 0.f, y1 = 0.f, x2 = 0.f, y2 = 0.f, ar = 0.f;
        int oi = -1;
        if (t < n) {
            unsigned key = skeys[t];
            if (key != INVALID_KEY) {
                oi = (int)svals[t];
                float4 b = g_boxes[oi];
                x1 = b.x; y1 = b.y; x2 = b.z; y2 = b.w;
                ar = (x2 - x1 + 1.0f) * (y2 - y1 + 1.0f);
                alive = true;
            }
        }
        cx1[tid] = x1; cy1[tid] = y1; cx2[tid] = x2; cy2[tid] = y2;
        car[tid] = ar; cid[tid] = oi;

        for (int k = 0; k < nk0; ++k) {
            if (!alive) break;
            if (iou_gt(kx1[k], ky1[k], kx2[k], ky2[k], kar[k], x1, y1, x2, y2, ar))
                alive = false;
        }

        for (;;) {
            unsigned m = __ballot_sync(FULL, alive);
            if (lane == 0) amask[warp] = m;
            __syncthreads();
            if (tid == 0) {
                int j = -1;
                int nk = s_nk;
                if (nk < MAX_KEEP) {
                    #pragma unroll
                    for (int w = 0; w < NMS_T / 32; ++w) {
                        unsigned mm = amask[w];
                        if (mm) { j = w * 32 + __ffs(mm) - 1; break; }
                    }
                }
                if (j >= 0) {
                    kx1[nk] = cx1[j]; ky1[nk] = cy1[j];
                    kx2[nk] = cx2[j]; ky2[nk] = cy2[j];
                    kar[nk] = car[j]; kid[nk] = cid[j];
                    s_nk = nk + 1;
                }
                s_j = j;
            }
            __syncthreads();
            int j = s_j;
            if (j < 0) break;
            if (alive) {
                if (tid == j) alive = false;
                else if (tid > j &&
                         iou_gt(cx1[j], cy1[j], cx2[j], cy2[j], car[j], x1, y1, x2, y2, ar))
                    alive = false;
            }
        }
    }

    __syncthreads();
    int nk = s_nk;
    for (int i = tid; i < MAX_KEEP; i += blockDim.x)
        g_kept[i] = (i < nk) ? kid[i] : -1;
}

// ---------------- K6: gather outputs (boxes | scores | landmarks) ------------------
__global__ void output_kernel(const float* __restrict__ sc,
                              const float* __restrict__ lm,
                              float* __restrict__ out) {
    int slot = blockIdx.x * blockDim.x + threadIdx.x;
    if (slot >= MAX_KEEP) return;
    int idx = g_kept[slot];
    float b0 = 0.f, b1 = 0.f, b2 = 0.f, b3 = 0.f, s = 0.f;
    float l[10];
    #pragma unroll
    for (int k = 0; k < 10; ++k) l[k] = 0.f;
    if (idx >= 0) {
        float4 b = g_boxes[idx];
        b0 = b.x; b1 = b.y; b2 = b.z; b3 = b.w;
        s = sc[idx];
        float px, py, ps;
        get_prior(idx, px, py, ps);
        #pragma unroll
        for (int k = 0; k < 5; ++k) {
            float ox = lm[10 * idx + 2 * k + 0];
            float oy = lm[10 * idx + 2 * k + 1];
            l[2 * k + 0] = (px + ox * 0.1f * ps) * 2560.0f;
            l[2 * k + 1] = (py + oy * 0.1f * ps) * 2560.0f;
        }
    }
    out[slot * 4 + 0] = b0;
    out[slot * 4 + 1] = b1;
    out[slot * 4 + 2] = b2;
    out[slot * 4 + 3] = b3;
    out[3000 + slot] = s;
    #pragma unroll
    for (int k = 0; k < 10; ++k)
        out[3750 + slot * 10 + k] = l[k];
}

// ---------------- launch ----------------------------------------------------------
extern "C" void kernel_launch(void* const* d_in, const int* in_sizes, int n_in,
                              void* d_out, int out_size) {
    const float* bb  = (const float*)d_in[0];
    const float* sc  = (const float*)d_in[1];
    const float* lm  = (const float*)d_in[2];
    const float* thr = (const float*)d_in[3];
    float* out = (float*)d_out;

    void *pk, *pv, *pks, *pvs, *ptmp;
    cudaGetSymbolAddress(&pk,   g_keys);
    cudaGetSymbolAddress(&pv,   g_vals);
    cudaGetSymbolAddress(&pks,  g_keys_s);
    cudaGetSymbolAddress(&pvs,  g_vals_s);
    cudaGetSymbolAddress(&ptmp, g_temp);

    decode_kernel<<<NP / 256, 256>>>(bb, sc, thr);

    size_t tb = 0;
    cub::DeviceRadixSort::SortPairs(nullptr, tb,
                                    (const unsigned*)pk, (unsigned*)pks,
                                    (const unsigned*)pv, (unsigned*)pvs,
                                    NP, 0, 32, (cudaStream_t)0);
    cub::DeviceRadixSort::SortPairs(ptmp, tb,
                                    (const unsigned*)pk, (unsigned*)pks,
                                    (const unsigned*)pv, (unsigned*)pvs,
                                    NP, 0, 32, (cudaStream_t)0);

    gather_kernel<<<H / 256, 256>>>((const unsigned*)pks, (const unsigned*)pvs);
    edges_kernel<<<(H * 32) / 256, 256>>>();
    resolve_kernel<<<1, H>>>((const unsigned*)pks);
    nms_fallback_kernel<<<1, NMS_T>>>((const unsigned*)pks, (const unsigned*)pvs, NP);

    output_kernel<<<(MAX_KEEP + 127) / 128, 128>>>(sc, lm, out);
}

// round 3
// speedup vs baseline: 6.4422x; 1.1224x over previous
#include <cuda_runtime.h>
#include <cub/cub.cuh>

#define NP 268800
#define MAX_KEEP 750
#define IOU_THR 0.4f
#define H 1024
#define HW (H / 32)
#define NB 2048
#define CAP 4096
#define TGT 2560
#define FULL 0xFFFFFFFFu
#define SENT 0xFFFFFFFFFFFFFFFFull

// ---------------- scratch (static device globals; no runtime alloc) ----------------
__device__ int                g_hist[NB];
__device__ int                g_cnt;
__device__ int                g_cut;
__device__ int                g_total;
__device__ unsigned long long g_ck[CAP];
__device__ unsigned long long g_sorted[CAP];
__device__ float4             g_cbox[H];
__device__ float              g_car[H];
__device__ int                g_cval[H];
__device__ int                g_cidx[H];
__device__ unsigned           g_E[H * HW];
__device__ int                g_kept[MAX_KEEP];
__device__ int                g_done;

// ---------------- priors computed on the fly (fp64 like numpy, cast to f32) --------
__device__ __forceinline__ void get_prior(int i, float& px, float& py, float& ps) {
    int j = i, f, step;
    double mins;
    if (j < 204800)      { f = 320; step = 8;  mins = (j & 1) ? 32.0  : 16.0;  }
    else if (j < 256000) { j -= 204800; f = 160; step = 16; mins = (j & 1) ? 128.0 : 64.0;  }
    else                 { j -= 256000; f = 80;  step = 32; mins = (j & 1) ? 512.0 : 256.0; }
    int cell = j >> 1;
    int y = cell / f;
    int x = cell - y * f;
    px = (float)(((double)x + 0.5) * (double)step / 2560.0);
    py = (float)(((double)y + 0.5) * (double)step / 2560.0);
    ps = (float)(mins / 2560.0);
}

__device__ __forceinline__ float4 decode_box(const float* __restrict__ bb, int i) {
    float px, py, ps;
    get_prior(i, px, py, ps);
    float lx = bb[4 * i + 0], ly = bb[4 * i + 1];
    float lw = bb[4 * i + 2], lh = bb[4 * i + 3];
    float cx = px + lx * 0.1f * ps;
    float cy = py + ly * 0.1f * ps;
    float w  = ps * expf(lw * 0.2f);
    float h  = ps * expf(lh * 0.2f);
    return make_float4((cx - w * 0.5f) * 2560.0f, (cy - h * 0.5f) * 2560.0f,
                       (cx + w * 0.5f) * 2560.0f, (cy + h * 0.5f) * 2560.0f);
}

__device__ __forceinline__ bool iou_gt(float x1, float y1, float x2, float y2, float ar,
                                       float bx1, float by1, float bx2, float by2, float bar) {
    float xx1 = fmaxf(x1, bx1), yy1 = fmaxf(y1, by1);
    float xx2 = fminf(x2, bx2), yy2 = fminf(y2, by2);
    float inter = fmaxf(0.0f, xx2 - xx1 + 1.0f) * fmaxf(0.0f, yy2 - yy1 + 1.0f);
    float iou = inter / (ar + bar - inter);
    return iou > IOU_THR;
}

// bucket is exactly monotone non-increasing in s (float ops are monotone here),
// so {bucket <= cut} is exactly an up-set in score incl. full tie groups.
__device__ __forceinline__ int bucketof(float s) {
    int b = (int)((1.0f - s) * (float)NB);
    return min(NB - 1, max(0, b));
}

// ---------------- K1: score histogram --------------------------------------------
__global__ void score_hist_kernel(const float* __restrict__ sc,
                                  const float* __restrict__ thrp) {
    __shared__ int sh[NB];
    int tid = threadIdx.x;
    for (int b = tid; b < NB; b += blockDim.x) sh[b] = 0;
    __syncthreads();
    float thr = thrp[0];
    for (int i = blockIdx.x * blockDim.x + tid; i < NP; i += gridDim.x * blockDim.x) {
        float s = sc[i];
        if (s > thr) atomicAdd(&sh[bucketof(s)], 1);
    }
    __syncthreads();
    for (int b = tid; b < NB; b += blockDim.x) {
        int v = sh[b];
        if (v) atomicAdd(&g_hist[b], v);
    }
}

// ---------------- K2: cutoff selection (1 block) ----------------------------------
__global__ void __launch_bounds__(1024, 1) cutoff_kernel() {
    typedef cub::BlockScan<int, 1024> BS;
    __shared__ typename BS::TempStorage ts;
    __shared__ int s_total, s_cut;
    int tid = threadIdx.x;
    int items[2] = { g_hist[2 * tid], g_hist[2 * tid + 1] };
    int incl[2];
    BS(ts).InclusiveSum(items, incl);
    if (tid == 1023) s_total = incl[1];
    if (tid == 0)    s_cut = NB - 1;
    __syncthreads();
    int total = s_total;
    int target = min(TGT, total);
    #pragma unroll
    for (int p = 0; p < 2; ++p)
        if (incl[p] >= target) atomicMin(&s_cut, 2 * tid + p);
    __syncthreads();
    if (tid == 0) { g_cut = s_cut; g_total = total; }
}

// ---------------- K3: compact candidates above cutoff ------------------------------
__global__ void compact_kernel(const float* __restrict__ sc,
                               const float* __restrict__ thrp) {
    int i = blockIdx.x * blockDim.x + threadIdx.x;
    if (i >= NP) return;
    float s = sc[i];
    float thr = thrp[0];
    int cut = g_cut;
    if (s > thr && bucketof(s) <= cut) {
        int pos = atomicAdd(&g_cnt, 1);
        if (pos < CAP)
            g_ck[pos] = ((unsigned long long)(~__float_as_uint(s)) << 32) | (unsigned)i;
    }
}

// ---------------- K4: bitonic sort (4096 u64) + top-H gather/decode ---------------
__global__ void __launch_bounds__(1024, 1)
sortgather_kernel(const float* __restrict__ bb) {
    __shared__ unsigned long long sh[CAP];
    int tid = threadIdx.x;
    int cnt = min(g_cnt, CAP);
    #pragma unroll
    for (int p = 0; p < CAP / 1024; ++p) {
        int i = tid + p * 1024;
        sh[i] = (i < cnt) ? g_ck[i] : SENT;
    }
    __syncthreads();
    // ascending u64 => score desc, index asc (stable tie order), sentinels last
    for (int k = 2; k <= CAP; k <<= 1) {
        for (int j = k >> 1; j > 0; j >>= 1) {
            #pragma unroll
            for (int p = 0; p < CAP / 1024; ++p) {
                int i = tid + p * 1024;
                int ixj = i ^ j;
                if (ixj > i) {
                    bool up = ((i & k) == 0);
                    unsigned long long a = sh[i], b = sh[ixj];
                    if ((a > b) == up) { sh[i] = b; sh[ixj] = a; }
                }
            }
            __syncthreads();
        }
    }
    #pragma unroll
    for (int p = 0; p < CAP / 1024; ++p) {
        int i = tid + p * 1024;
        g_sorted[i] = sh[i];
    }
    // gather + decode top-H
    unsigned long long v = sh[tid];
    bool valid = (v != SENT);
    int idx = (int)(v & 0xFFFFFFFFull);
    float4 b = make_float4(0.f, 0.f, 0.f, 0.f);
    if (valid) b = decode_box(bb, idx);
    g_cbox[tid] = b;
    g_car[tid]  = (b.z - b.x + 1.0f) * (b.w - b.y + 1.0f);
    g_cval[tid] = valid ? 1 : 0;
    g_cidx[tid] = valid ? idx : -1;
}

// ---------------- K5: pairwise earlier-neighbor edge matrix (multi-SM) -------------
__global__ void edges_kernel() {
    int j = (blockIdx.x * blockDim.x + threadIdx.x) >> 5;   // one warp per row
    int lane = threadIdx.x & 31;
    if (j >= H) return;
    float4 bj = g_cbox[j];
    float  aj = g_car[j];
    bool   vj = g_cval[j] != 0;
    unsigned myword = 0;
    #pragma unroll 4
    for (int w = 0; w < HW; ++w) {
        int i = w * 32 + lane;
        float4 bi = g_cbox[i];
        float  ai = g_car[i];
        bool pred = vj && (g_cval[i] != 0) && (i < j) &&
                    iou_gt(bj.x, bj.y, bj.z, bj.w, aj, bi.x, bi.y, bi.z, bi.w, ai);
        unsigned m = __ballot_sync(FULL, pred);
        if (lane == w) myword = m;
    }
    g_E[j * HW + lane] = myword;
}

// ---------------- K6: parallel greedy resolution (1 block) -------------------------
__global__ void __launch_bounds__(H, 1)
resolve_kernel() {
    __shared__ unsigned dec[HW], kep[HW];
    __shared__ int woff[33];
    int tid = threadIdx.x;
    int lane = tid & 31;
    int warp = tid >> 5;

    unsigned E[HW];
    {
        const uint4* row = (const uint4*)&g_E[tid * HW];
        #pragma unroll
        for (int q = 0; q < HW / 4; ++q) {
            uint4 v = row[q];
            E[4 * q + 0] = v.x; E[4 * q + 1] = v.y; E[4 * q + 2] = v.z; E[4 * q + 3] = v.w;
        }
    }
    bool valid   = g_cval[tid] != 0;
    bool decided = !valid;
    bool kept    = false;

    {
        unsigned md = __ballot_sync(FULL, decided);
        if (lane == 0) { dec[warp] = md; kep[warp] = 0u; }
    }
    __syncthreads();

    for (int round = 0; round < 64; ++round) {
        if (!decided) {
            unsigned pend = 0, sup = 0;
            #pragma unroll
            for (int w = 0; w < HW; ++w) {
                unsigned d = dec[w], k = kep[w], e = E[w];
                pend |= e & ~d;
                sup  |= e & k;
            }
            if (pend == 0u) { decided = true; kept = (sup == 0u); }
        }
        __syncthreads();
        unsigned md = __ballot_sync(FULL, decided);
        unsigned mk = __ballot_sync(FULL, kept);
        if (lane == 0) { dec[warp] = md; kep[warp] = mk; }
        int nUnd = __syncthreads_count(decided ? 0 : 1);
        if (nUnd == 0) break;
    }

    // exact serial fallback for pathological chains (never triggers on real data)
    int rem = __syncthreads_count(decided ? 0 : 1);
    if (rem > 0) {
        if (tid == 0) {
            for (int v = 0; v < H; ++v) {
                int w = v >> 5, b = v & 31;
                if ((dec[w] >> b) & 1u) continue;
                unsigned sup = 0;
                for (int ww = 0; ww < HW; ++ww) sup |= g_E[v * HW + ww] & kep[ww];
                dec[w] |= 1u << b;
                if (sup == 0u) kep[w] |= 1u << b;
            }
        }
        __syncthreads();
        kept = (kep[tid >> 5] >> (tid & 31)) & 1u;
    }

    // rank kept candidates in order; write first MAX_KEEP
    unsigned m = __ballot_sync(FULL, kept);
    if (lane == 0) woff[warp] = __popc(m);
    __syncthreads();
    if (tid < 32) {
        int v = woff[tid];
        int ex = v;
        #pragma unroll
        for (int d = 1; d < 32; d <<= 1) {
            int t = __shfl_up_sync(FULL, ex, d);
            if (tid >= d) ex += t;
        }
        woff[tid] = ex - v;                 // exclusive
        if (tid == 31) woff[32] = ex;       // total
    }
    __syncthreads();
    int total = woff[32];

    if (tid < MAX_KEEP) g_kept[tid] = -1;
    __syncthreads();
    if (kept) {
        int rank = woff[warp] + __popc(m & ((1u << lane) - 1u));
        if (rank < MAX_KEEP) g_kept[rank] = g_cidx[tid];
    }
    if (tid == 0)
        g_done = (total >= MAX_KEEP) || (g_total <= H) ? 1 : 0;
}

// ---------------- K7: exact fallback NMS over sorted compacted list (gated) --------
#define NMS_T 1024
__global__ void __launch_bounds__(NMS_T, 1)
nms_fallback_kernel(const float* __restrict__ bb) {
    if (g_done) return;
    __shared__ float kx1[MAX_KEEP], ky1[MAX_KEEP], kx2[MAX_KEEP], ky2[MAX_KEEP], kar[MAX_KEEP];
    __shared__ int   kid[MAX_KEEP];
    __shared__ float cx1[NMS_T], cy1[NMS_T], cx2[NMS_T], cy2[NMS_T], car[NMS_T];
    __shared__ int   cid[NMS_T];
    __shared__ unsigned amask[NMS_T / 32];
    __shared__ int s_nk, s_j;

    int tid  = threadIdx.x;
    int lane = tid & 31;
    int warp = tid >> 5;
    if (tid == 0) s_nk = 0;
    __syncthreads();

    for (int base = 0; base < CAP; base += NMS_T) {
        int nk0 = s_nk;
        if (nk0 >= MAX_KEEP) break;
        if (g_sorted[base] == SENT) break;

        int t = base + tid;
        bool alive = false;
        float x1 = 0.f, y1 = 0.f, x2 = 0.f, y2 = 0.f, ar = 0.f;
        int oi = -1;
        unsigned long long v = g_sorted[t];
        if (v != SENT) {
            oi = (int)(v & 0xFFFFFFFFull);
            float4 b = decode_box(bb, oi);
            x1 = b.x; y1 = b.y; x2 = b.z; y2 = b.w;
            ar = (x2 - x1 + 1.0f) * (y2 - y1 + 1.0f);
            alive = true;
        }
        cx1[tid] = x1; cy1[tid] = y1; cx2[tid] = x2; cy2[tid] = y2;
        car[tid] = ar; cid[tid] = oi;

        for (int k = 0; k < nk0; ++k) {
            if (!alive) break;
            if (iou_gt(kx1[k], ky1[k], kx2[k], ky2[k], kar[k], x1, y1, x2, y2, ar))
                alive = false;
        }

        for (;;) {
            unsigned m = __ballot_sync(FULL, alive);
            if (lane == 0) amask[warp] = m;
            __syncthreads();
            if (tid == 0) {
                int j = -1;
                int nk = s_nk;
                if (nk < MAX_KEEP) {
                    #pragma unroll
                    for (int w = 0; w < NMS_T / 32; ++w) {
                        unsigned mm = amask[w];
                        if (mm) { j = w * 32 + __ffs(mm) - 1; break; }
                    }
                }
                if (j >= 0) {
                    kx1[nk] = cx1[j]; ky1[nk] = cy1[j];
                    kx2[nk] = cx2[j]; ky2[nk] = cy2[j];
                    kar[nk] = car[j]; kid[nk] = cid[j];
                    s_nk = nk + 1;
                }
                s_j = j;
            }
            __syncthreads();
            int j = s_j;
            if (j < 0) break;
            if (alive) {
                if (tid == j) alive = false;
                else if (tid > j &&
                         iou_gt(cx1[j], cy1[j], cx2[j], cy2[j], car[j], x1, y1, x2, y2, ar))
                    alive = false;
            }
        }
    }

    __syncthreads();
    int nk = s_nk;
    for (int i = tid; i < MAX_KEEP; i += blockDim.x)
        g_kept[i] = (i < nk) ? kid[i] : -1;
}

// ---------------- K8: gather outputs (boxes | scores | landmarks) ------------------
__global__ void output_kernel(const float* __restrict__ bb,
                              const float* __restrict__ sc,
                              const float* __restrict__ lm,
                              float* __restrict__ out) {
    int slot = blockIdx.x * blockDim.x + threadIdx.x;
    if (slot >= MAX_KEEP) return;
    int idx = g_kept[slot];
    float b0 = 0.f, b1 = 0.f, b2 = 0.f, b3 = 0.f, s = 0.f;
    float l[10];
    #pragma unroll
    for (int k = 0; k < 10; ++k) l[k] = 0.f;
    if (idx >= 0) {
        float4 b = decode_box(bb, idx);
        b0 = b.x; b1 = b.y; b2 = b.z; b3 = b.w;
        s = sc[idx];
        float px, py, ps;
        get_prior(idx, px, py, ps);
        #pragma unroll
        for (int k = 0; k < 5; ++k) {
            float ox = lm[10 * idx + 2 * k + 0];
            float oy = lm[10 * idx + 2 * k + 1];
            l[2 * k + 0] = (px + ox * 0.1f * ps) * 2560.0f;
            l[2 * k + 1] = (py + oy * 0.1f * ps) * 2560.0f;
        }
    }
    out[slot * 4 + 0] = b0;
    out[slot * 4 + 1] = b1;
    out[slot * 4 + 2] = b2;
    out[slot * 4 + 3] = b3;
    out[3000 + slot] = s;
    #pragma unroll
    for (int k = 0; k < 10; ++k)
        out[3750 + slot * 10 + k] = l[k];
}

// ---------------- launch ----------------------------------------------------------
extern "C" void kernel_launch(void* const* d_in, const int* in_sizes, int n_in,
                              void* d_out, int out_size) {
    const float* bb  = (const float*)d_in[0];
    const float* sc  = (const float*)d_in[1];
    const float* lm  = (const float*)d_in[2];
    const float* thr = (const float*)d_in[3];
    float* out = (float*)d_out;

    void *phist, *pcnt;
    cudaGetSymbolAddress(&phist, g_hist);
    cudaGetSymbolAddress(&pcnt,  g_cnt);
    cudaMemsetAsync(phist, 0, NB * sizeof(int), 0);
    cudaMemsetAsync(pcnt,  0, sizeof(int), 0);

    score_hist_kernel<<<128, 256>>>(sc, thr);
    cutoff_kernel<<<1, 1024>>>();
    compact_kernel<<<NP / 256, 256>>>(sc, thr);
    sortgather_kernel<<<1, 1024>>>(bb);
    edges_kernel<<<(H * 32) / 256, 256>>>();
    resolve_kernel<<<1, H>>>();
    nms_fallback_kernel<<<1, NMS_T>>>(bb);
    output_kernel<<<(MAX_KEEP + 127) / 128, 128>>>(bb, sc, lm, out);
}

// round 4
// speedup vs baseline: 10.5359x; 1.6354x over previous
#include <cuda_runtime.h>
#include <cub/cub.cuh>

#define NP 268800
#define MAX_KEEP 750
#define IOU_THR 0.4f
#define H 1024
#define HW (H / 32)
#define NB 2048
#define CAP 4096
#define TGT 2560
#define FULL 0xFFFFFFFFu
#define SENT 0xFFFFFFFFFFFFFFFFull

// ---------------- scratch (static device globals; no runtime alloc) ----------------
__device__ int                g_hist[NB];
__device__ int                g_cnt;
__device__ int                g_cut;
__device__ int                g_total;
__device__ unsigned long long g_ck[CAP];
__device__ unsigned long long g_sorted[CAP];
__device__ float4             g_cbox[H];
__device__ float              g_car[H];
__device__ int                g_cval[H];
__device__ int                g_cidx[H];
__device__ unsigned           g_E[H * HW];
__device__ int                g_kept[MAX_KEEP];
__device__ int                g_done;

// ---------------- priors computed on the fly (fp64 like numpy, cast to f32) --------
__device__ __forceinline__ void get_prior(int i, float& px, float& py, float& ps) {
    int j = i, f, step;
    double mins;
    if (j < 204800)      { f = 320; step = 8;  mins = (j & 1) ? 32.0  : 16.0;  }
    else if (j < 256000) { j -= 204800; f = 160; step = 16; mins = (j & 1) ? 128.0 : 64.0;  }
    else                 { j -= 256000; f = 80;  step = 32; mins = (j & 1) ? 512.0 : 256.0; }
    int cell = j >> 1;
    int y = cell / f;
    int x = cell - y * f;
    px = (float)(((double)x + 0.5) * (double)step / 2560.0);
    py = (float)(((double)y + 0.5) * (double)step / 2560.0);
    ps = (float)(mins / 2560.0);
}

__device__ __forceinline__ float4 decode_box(const float* __restrict__ bb, int i) {
    float px, py, ps;
    get_prior(i, px, py, ps);
    float lx = bb[4 * i + 0], ly = bb[4 * i + 1];
    float lw = bb[4 * i + 2], lh = bb[4 * i + 3];
    float cx = px + lx * 0.1f * ps;
    float cy = py + ly * 0.1f * ps;
    float w  = ps * expf(lw * 0.2f);
    float h  = ps * expf(lh * 0.2f);
    return make_float4((cx - w * 0.5f) * 2560.0f, (cy - h * 0.5f) * 2560.0f,
                       (cx + w * 0.5f) * 2560.0f, (cy + h * 0.5f) * 2560.0f);
}

__device__ __forceinline__ bool iou_gt(float x1, float y1, float x2, float y2, float ar,
                                       float bx1, float by1, float bx2, float by2, float bar) {
    float xx1 = fmaxf(x1, bx1), yy1 = fmaxf(y1, by1);
    float xx2 = fminf(x2, bx2), yy2 = fminf(y2, by2);
    float inter = fmaxf(0.0f, xx2 - xx1 + 1.0f) * fmaxf(0.0f, yy2 - yy1 + 1.0f);
    float iou = inter / (ar + bar - inter);
    return iou > IOU_THR;
}

// bucket is exactly monotone non-increasing in s, so {bucket <= cut} is exactly an
// up-set in score incl. full tie groups.
__device__ __forceinline__ int bucketof(float s) {
    int b = (int)((1.0f - s) * (float)NB);
    return min(NB - 1, max(0, b));
}

// ---------------- K0: init all state (replaces memsets) ---------------------------
__global__ void init_kernel() {
    int i = blockIdx.x * blockDim.x + threadIdx.x;
    if (i < NB) g_hist[i] = 0;
    if (i == 0) { g_cnt = 0; g_done = 0; }
    if (i < CAP) g_sorted[i] = SENT;
    if (i < H) {
        g_cbox[i] = make_float4(0.f, 0.f, 0.f, 0.f);
        g_car[i]  = 1.0f;
        g_cval[i] = 0;
        g_cidx[i] = -1;
    }
}

// ---------------- K1: score histogram ----------------------------------------------
__global__ void score_hist_kernel(const float* __restrict__ sc,
                                  const float* __restrict__ thrp) {
    __shared__ int sh[NB];
    int tid = threadIdx.x;
    for (int b = tid; b < NB; b += blockDim.x) sh[b] = 0;
    __syncthreads();
    float thr = thrp[0];
    for (int i = blockIdx.x * blockDim.x + tid; i < NP; i += gridDim.x * blockDim.x) {
        float s = sc[i];
        if (s > thr) atomicAdd(&sh[bucketof(s)], 1);
    }
    __syncthreads();
    for (int b = tid; b < NB; b += blockDim.x) {
        int v = sh[b];
        if (v) atomicAdd(&g_hist[b], v);
    }
}

// ---------------- K2: cutoff selection (1 block) ----------------------------------
__global__ void __launch_bounds__(1024, 1) cutoff_kernel() {
    typedef cub::BlockScan<int, 1024> BS;
    __shared__ typename BS::TempStorage ts;
    __shared__ int s_total, s_cut;
    int tid = threadIdx.x;
    int items[2] = { g_hist[2 * tid], g_hist[2 * tid + 1] };
    int incl[2];
    BS(ts).InclusiveSum(items, incl);
    if (tid == 1023) s_total = incl[1];
    if (tid == 0)    s_cut = NB - 1;
    __syncthreads();
    int total = s_total;
    int target = min(TGT, total);
    #pragma unroll
    for (int p = 0; p < 2; ++p)
        if (incl[p] >= target) atomicMin(&s_cut, 2 * tid + p);
    __syncthreads();
    if (tid == 0) { g_cut = s_cut; g_total = total; }
}

// ---------------- K3: compact candidates above cutoff ------------------------------
__global__ void compact_kernel(const float* __restrict__ sc,
                               const float* __restrict__ thrp) {
    int i = blockIdx.x * blockDim.x + threadIdx.x;
    if (i >= NP) return;
    float s = sc[i];
    float thr = thrp[0];
    int cut = g_cut;
    if (s > thr && bucketof(s) <= cut) {
        int pos = atomicAdd(&g_cnt, 1);
        if (pos < CAP)
            g_ck[pos] = ((unsigned long long)(~__float_as_uint(s)) << 32) | (unsigned)i;
    }
}

// ---------------- K4: rank-scatter sort (warp per element) + top-H decode ----------
// keys unique (idx in low 32 bits) => rank = #{smaller keys} is an exact permutation,
// ascending u64 == (score desc, index asc) stable order.
__global__ void ranksort_kernel(const float* __restrict__ bb) {
    int e    = (blockIdx.x * blockDim.x + threadIdx.x) >> 5;
    int lane = threadIdx.x & 31;
    int cnt  = min(g_cnt, CAP);
    if (e >= cnt) return;
    unsigned long long ki = g_ck[e];
    int r = 0;
    for (int j = lane; j < cnt; j += 32)
        r += (g_ck[j] < ki) ? 1 : 0;
    #pragma unroll
    for (int d = 16; d > 0; d >>= 1)
        r += __shfl_down_sync(FULL, r, d);
    r = __shfl_sync(FULL, r, 0);
    if (lane == 0) {
        g_sorted[r] = ki;
        if (r < H) {
            int idx = (int)(ki & 0xFFFFFFFFull);
            float4 b = decode_box(bb, idx);
            g_cbox[r] = b;
            g_car[r]  = (b.z - b.x + 1.0f) * (b.w - b.y + 1.0f);
            g_cval[r] = 1;
            g_cidx[r] = idx;
        }
    }
}

// ---------------- K5: pairwise earlier-neighbor edge matrix (multi-SM) -------------
__global__ void edges_kernel() {
    int j = (blockIdx.x * blockDim.x + threadIdx.x) >> 5;   // one warp per row
    int lane = threadIdx.x & 31;
    if (j >= H) return;
    float4 bj = g_cbox[j];
    float  aj = g_car[j];
    bool   vj = g_cval[j] != 0;
    unsigned myword = 0;
    #pragma unroll 4
    for (int w = 0; w < HW; ++w) {
        int i = w * 32 + lane;
        float4 bi = g_cbox[i];
        float  ai = g_car[i];
        bool pred = vj && (g_cval[i] != 0) && (i < j) &&
                    iou_gt(bj.x, bj.y, bj.z, bj.w, aj, bi.x, bi.y, bi.z, bi.w, ai);
        unsigned m = __ballot_sync(FULL, pred);
        if (lane == w) myword = m;
    }
    g_E[j * HW + lane] = myword;
}

// ---------------- K6: parallel greedy resolution (1 block) -------------------------
__global__ void __launch_bounds__(H, 1)
resolve_kernel() {
    __shared__ unsigned dec[HW], kep[HW];
    __shared__ int woff[33];
    int tid = threadIdx.x;
    int lane = tid & 31;
    int warp = tid >> 5;

    unsigned E[HW];
    {
        const uint4* row = (const uint4*)&g_E[tid * HW];
        #pragma unroll
        for (int q = 0; q < HW / 4; ++q) {
            uint4 v = row[q];
            E[4 * q + 0] = v.x; E[4 * q + 1] = v.y; E[4 * q + 2] = v.z; E[4 * q + 3] = v.w;
        }
    }
    bool valid   = g_cval[tid] != 0;
    bool decided = !valid;
    bool kept    = false;

    {
        unsigned md = __ballot_sync(FULL, decided);
        if (lane == 0) { dec[warp] = md; kep[warp] = 0u; }
    }
    __syncthreads();

    for (int round = 0; round < 64; ++round) {
        if (!decided) {
            unsigned pend = 0, sup = 0;
            #pragma unroll
            for (int w = 0; w < HW; ++w) {
                unsigned d = dec[w], k = kep[w], e = E[w];
                pend |= e & ~d;
                sup  |= e & k;
            }
            if (pend == 0u) { decided = true; kept = (sup == 0u); }
        }
        __syncthreads();
        unsigned md = __ballot_sync(FULL, decided);
        unsigned mk = __ballot_sync(FULL, kept);
        if (lane == 0) { dec[warp] = md; kep[warp] = mk; }
        int nUnd = __syncthreads_count(decided ? 0 : 1);
        if (nUnd == 0) break;
    }

    // exact serial fallback for pathological chains (never triggers on real data)
    int rem = __syncthreads_count(decided ? 0 : 1);
    if (rem > 0) {
        if (tid == 0) {
            for (int v = 0; v < H; ++v) {
                int w = v >> 5, b = v & 31;
                if ((dec[w] >> b) & 1u) continue;
                unsigned sup = 0;
                for (int ww = 0; ww < HW; ++ww) sup |= g_E[v * HW + ww] & kep[ww];
                dec[w] |= 1u << b;
                if (sup == 0u) kep[w] |= 1u << b;
            }
        }
        __syncthreads();
        kept = (kep[tid >> 5] >> (tid & 31)) & 1u;
    }

    // rank kept candidates in order; write first MAX_KEEP
    unsigned m = __ballot_sync(FULL, kept);
    if (lane == 0) woff[warp] = __popc(m);
    __syncthreads();
    if (tid < 32) {
        int v = woff[tid];
        int ex = v;
        #pragma unroll
        for (int d = 1; d < 32; d <<= 1) {
            int t = __shfl_up_sync(FULL, ex, d);
            if (tid >= d) ex += t;
        }
        woff[tid] = ex - v;                 // exclusive
        if (tid == 31) woff[32] = ex;       // total
    }
    __syncthreads();
    int total = woff[32];

    if (tid < MAX_KEEP) g_kept[tid] = -1;
    __syncthreads();
    if (kept) {
        int rank = woff[warp] + __popc(m & ((1u << lane) - 1u));
        if (rank < MAX_KEEP) g_kept[rank] = g_cidx[tid];
    }
    if (tid == 0)
        g_done = (total >= MAX_KEEP) || (g_total <= H) ? 1 : 0;
}

// ---------------- K7: exact fallback NMS over sorted compacted list (gated) --------
#define NMS_T 1024
__global__ void __launch_bounds__(NMS_T, 1)
nms_fallback_kernel(const float* __restrict__ bb) {
    if (g_done) return;
    __shared__ float kx1[MAX_KEEP], ky1[MAX_KEEP], kx2[MAX_KEEP], ky2[MAX_KEEP], kar[MAX_KEEP];
    __shared__ int   kid[MAX_KEEP];
    __shared__ float cx1[NMS_T], cy1[NMS_T], cx2[NMS_T], cy2[NMS_T], car[NMS_T];
    __shared__ int   cid[NMS_T];
    __shared__ unsigned amask[NMS_T / 32];
    __shared__ int s_nk, s_j;

    int tid  = threadIdx.x;
    int lane = tid & 31;
    int warp = tid >> 5;
    if (tid == 0) s_nk = 0;
    __syncthreads();

    for (int base = 0; base < CAP; base += NMS_T) {
        int nk0 = s_nk;
        if (nk0 >= MAX_KEEP) break;
        if (g_sorted[base] == SENT) break;

        int t = base + tid;
        bool alive = false;
        float x1 = 0.f, y1 = 0.f, x2 = 0.f, y2 = 0.f, ar = 0.f;
        int oi = -1;
        unsigned long long v = g_sorted[t];
        if (v != SENT) {
            oi = (int)(v & 0xFFFFFFFFull);
            float4 b = decode_box(bb, oi);
            x1 = b.x; y1 = b.y; x2 = b.z; y2 = b.w;
            ar = (x2 - x1 + 1.0f) * (y2 - y1 + 1.0f);
            alive = true;
        }
        cx1[tid] = x1; cy1[tid] = y1; cx2[tid] = x2; cy2[tid] = y2;
        car[tid] = ar; cid[tid] = oi;

        for (int k = 0; k < nk0; ++k) {
            if (!alive) break;
            if (iou_gt(kx1[k], ky1[k], kx2[k], ky2[k], kar[k], x1, y1, x2, y2, ar))
                alive = false;
        }

        for (;;) {
            unsigned m = __ballot_sync(FULL, alive);
            if (lane == 0) amask[warp] = m;
            __syncthreads();
            if (tid == 0) {
                int j = -1;
                int nk = s_nk;
                if (nk < MAX_KEEP) {
                    #pragma unroll
                    for (int w = 0; w < NMS_T / 32; ++w) {
                        unsigned mm = amask[w];
                        if (mm) { j = w * 32 + __ffs(mm) - 1; break; }
                    }
                }
                if (j >= 0) {
                    kx1[nk] = cx1[j]; ky1[nk] = cy1[j];
                    kx2[nk] = cx2[j]; ky2[nk] = cy2[j];
                    kar[nk] = car[j]; kid[nk] = cid[j];
                    s_nk = nk + 1;
                }
                s_j = j;
            }
            __syncthreads();
            int j = s_j;
            if (j < 0) break;
            if (alive) {
                if (tid == j) alive = false;
                else if (tid > j &&
                         iou_gt(cx1[j], cy1[j], cx2[j], cy2[j], car[j], x1, y1, x2, y2, ar))
                    alive = false;
            }
        }
    }

    __syncthreads();
    int nk = s_nk;
    for (int i = tid; i < MAX_KEEP; i += blockDim.x)
        g_kept[i] = (i < nk) ? kid[i] : -1;
}

// ---------------- K8: gather outputs (boxes | scores | landmarks) ------------------
__global__ void output_kernel(const float* __restrict__ bb,
                              const float* __restrict__ sc,
                              const float* __restrict__ lm,
                              float* __restrict__ out) {
    int slot = blockIdx.x * blockDim.x + threadIdx.x;
    if (slot >= MAX_KEEP) return;
    int idx = g_kept[slot];
    float b0 = 0.f, b1 = 0.f, b2 = 0.f, b3 = 0.f, s = 0.f;
    float l[10];
    #pragma unroll
    for (int k = 0; k < 10; ++k) l[k] = 0.f;
    if (idx >= 0) {
        float4 b = decode_box(bb, idx);
        b0 = b.x; b1 = b.y; b2 = b.z; b3 = b.w;
        s = sc[idx];
        float px, py, ps;
        get_prior(idx, px, py, ps);
        #pragma unroll
        for (int k = 0; k < 5; ++k) {
            float ox = lm[10 * idx + 2 * k + 0];
            float oy = lm[10 * idx + 2 * k + 1];
            l[2 * k + 0] = (px + ox * 0.1f * ps) * 2560.0f;
            l[2 * k + 1] = (py + oy * 0.1f * ps) * 2560.0f;
        }
    }
    out[slot * 4 + 0] = b0;
    out[slot * 4 + 1] = b1;
    out[slot * 4 + 2] = b2;
    out[slot * 4 + 3] = b3;
    out[3000 + slot] = s;
    #pragma unroll
    for (int k = 0; k < 10; ++k)
        out[3750 + slot * 10 + k] = l[k];
}

// ---------------- launch ----------------------------------------------------------
extern "C" void kernel_launch(void* const* d_in, const int* in_sizes, int n_in,
                              void* d_out, int out_size) {
    const float* bb  = (const float*)d_in[0];
    const float* sc  = (const float*)d_in[1];
    const float* lm  = (const float*)d_in[2];
    const float* thr = (const float*)d_in[3];
    float* out = (float*)d_out;

    init_kernel<<<CAP / 256, 256>>>();
    score_hist_kernel<<<128, 256>>>(sc, thr);
    cutoff_kernel<<<1, 1024>>>();
    compact_kernel<<<NP / 256, 256>>>(sc, thr);
    ranksort_kernel<<<(CAP * 32) / 1024, 1024>>>(bb);
    edges_kernel<<<(H * 32) / 256, 256>>>();
    resolve_kernel<<<1, H>>>();
    nms_fallback_kernel<<<1, NMS_T>>>(bb);
    output_kernel<<<(MAX_KEEP + 127) / 128, 128>>>(bb, sc, lm, out);
}